// round 1
// baseline (speedup 1.0000x reference)
#include <cuda_runtime.h>

#define Bsz 4
#define Sl 4096
#define Dm 1024
#define Hh 16
#define HD 64
#define SPLIT 16
#define BH (Bsz * Hh)

// Scratch (allocation-free rule: device globals)
__device__ float g_KV_part[SPLIT * BH * HD * HD];   // 16 MB
__device__ float g_KV[BH * HD * HD];                // 1 MB
__device__ float g_W2[Bsz * Dm * Dm];               // 16 MB

// ---------------------------------------------------------------------------
// Kernel A: partial KV[b,h,d,e] = sum_{s in split} K[b,s,h*64+d]*V[b,s,h*64+e]
// grid (BH, SPLIT), block 256. Each thread: 4x4 outputs.
// ---------------------------------------------------------------------------
__global__ __launch_bounds__(256) void kv_partial_kernel(
    const float* __restrict__ K, const float* __restrict__ V)
{
    int bh = blockIdx.x;
    int sp = blockIdx.y;
    int b = bh >> 4, h = bh & 15;
    int t = threadIdx.x;

    __shared__ float Ks[32][64];
    __shared__ float Vs[32][64];

    float acc[4][4] = {};
    int d0 = (t & 15) * 4;
    int e0 = (t >> 4) * 4;

    const float* Kbase = K + ((size_t)b * Sl) * Dm + h * HD;
    const float* Vbase = V + ((size_t)b * Sl) * Dm + h * HD;
    int s_begin = sp * (Sl / SPLIT);

    for (int sc = 0; sc < (Sl / SPLIT); sc += 32) {
#pragma unroll
        for (int r = 0; r < 2; r++) {
            int idx = t + r * 256;
            int row = idx >> 4;
            int c4 = (idx & 15) * 4;
            size_t goff = (size_t)(s_begin + sc + row) * Dm + c4;
            float4 kv4 = *(const float4*)(Kbase + goff);
            float4 vv4 = *(const float4*)(Vbase + goff);
            *(float4*)&Ks[row][c4] = kv4;
            *(float4*)&Vs[row][c4] = vv4;
        }
        __syncthreads();
#pragma unroll
        for (int ss = 0; ss < 32; ss++) {
            float4 kd = *(const float4*)&Ks[ss][d0];
            float4 ve = *(const float4*)&Vs[ss][e0];
            float kk[4] = {kd.x, kd.y, kd.z, kd.w};
            float vv[4] = {ve.x, ve.y, ve.z, ve.w};
#pragma unroll
            for (int i = 0; i < 4; i++)
#pragma unroll
                for (int j = 0; j < 4; j++)
                    acc[i][j] += kk[i] * vv[j];
        }
        __syncthreads();
    }

    float* out = g_KV_part + ((size_t)sp * BH + bh) * (HD * HD);
#pragma unroll
    for (int i = 0; i < 4; i++)
#pragma unroll
        for (int j = 0; j < 4; j++)
            out[(d0 + i) * HD + (e0 + j)] = acc[i][j];
}

// ---------------------------------------------------------------------------
// Kernel B: deterministic reduction of the SPLIT partials
// ---------------------------------------------------------------------------
__global__ __launch_bounds__(256) void kv_reduce_kernel()
{
    int idx = blockIdx.x * 256 + threadIdx.x;   // 262144 total
    float s = 0.f;
#pragma unroll
    for (int p = 0; p < SPLIT; p++)
        s += g_KV_part[(size_t)p * (BH * HD * HD) + idx];
    g_KV[idx] = s;
}

// ---------------------------------------------------------------------------
// Kernel C: W2[b][o][h*64+d] = sum_e KV[b,h,d,e] * W[o*Dm + h*64 + e]
// grid (BH, Dm/64), block 256. 64(o) x 64(d) tile, 4x4 per thread.
// ---------------------------------------------------------------------------
__global__ __launch_bounds__(256) void w2_kernel(const float* __restrict__ W)
{
    int bh = blockIdx.x;
    int ot = blockIdx.y;
    int b = bh >> 4, h = bh & 15;
    int t = threadIdx.x;
    int o_base = ot * 64;

    __shared__ float KVt[64][68];   // [e][d], padded
    __shared__ float WsT[64][68];   // [e][o], padded

    for (int idx = t; idx < 4096; idx += 256) {
        int r = idx >> 6;        // d (for KV) / o (for W)
        int c = idx & 63;        // e
        KVt[c][r] = g_KV[(size_t)bh * 4096 + idx];
        WsT[c][r] = W[(size_t)(o_base + r) * Dm + h * HD + c];
    }
    __syncthreads();

    int d0 = (t & 15) * 4;
    int o0 = (t >> 4) * 4;
    float acc[4][4] = {};
#pragma unroll 8
    for (int e = 0; e < 64; e++) {
        float4 wv = *(const float4*)&WsT[e][o0];
        float4 kv = *(const float4*)&KVt[e][d0];
        float ww[4] = {wv.x, wv.y, wv.z, wv.w};
        float kk[4] = {kv.x, kv.y, kv.z, kv.w};
#pragma unroll
        for (int i = 0; i < 4; i++)
#pragma unroll
            for (int j = 0; j < 4; j++)
                acc[i][j] += ww[i] * kk[j];
    }
#pragma unroll
    for (int i = 0; i < 4; i++)
#pragma unroll
        for (int j = 0; j < 4; j++)
            g_W2[((size_t)b * Dm + (o_base + o0 + i)) * Dm + h * HD + d0 + j] = acc[i][j];
}

// ---------------------------------------------------------------------------
// Kernel D: out[b,m,n] = sum_k Q[b,m,k] * W2[b,n,k] + bias[n]
// Classic 128x128x8 SGEMM (NT), double-buffered, 8x8 per thread.
// grid (Sl/128, Dm/128, Bsz), block 256.
// ---------------------------------------------------------------------------
__global__ __launch_bounds__(256) void out_gemm_kernel(
    const float* __restrict__ Q, const float* __restrict__ bias,
    float* __restrict__ Out)
{
    int bm = blockIdx.x;
    int bn = blockIdx.y;
    int b  = blockIdx.z;

    const float* A  = Q    + (size_t)b * Sl * Dm;
    const float* Bm = g_W2 + (size_t)b * Dm * Dm;
    float*       C  = Out  + (size_t)b * Sl * Dm;

    __shared__ float As[2][8][128];
    __shared__ float Bs[2][8][128];

    int t  = threadIdx.x;
    int tx = t & 15, ty = t >> 4;
    int m0 = bm * 128, n0 = bn * 128;

    int lr = t >> 1;            // tile row 0..127
    int lk = (t & 1) * 4;       // k sub-offset {0,4}

    float acc[8][8] = {};

    {
        float4 av = *(const float4*)(A  + (size_t)(m0 + lr) * Dm + lk);
        float4 bv = *(const float4*)(Bm + (size_t)(n0 + lr) * Dm + lk);
        As[0][lk + 0][lr] = av.x; As[0][lk + 1][lr] = av.y;
        As[0][lk + 2][lr] = av.z; As[0][lk + 3][lr] = av.w;
        Bs[0][lk + 0][lr] = bv.x; Bs[0][lk + 1][lr] = bv.y;
        Bs[0][lk + 2][lr] = bv.z; Bs[0][lk + 3][lr] = bv.w;
    }
    __syncthreads();

    const int NK = Dm / 8;      // 128 chunks
    for (int kc = 0; kc < NK; kc++) {
        int cur = kc & 1, nxt = cur ^ 1;
        float4 av, bv;
        bool pre = (kc + 1 < NK);
        if (pre) {
            int k0 = (kc + 1) * 8;
            av = *(const float4*)(A  + (size_t)(m0 + lr) * Dm + k0 + lk);
            bv = *(const float4*)(Bm + (size_t)(n0 + lr) * Dm + k0 + lk);
        }
#pragma unroll
        for (int k = 0; k < 8; k++) {
            float a[8], bb[8];
            *(float4*)&a[0]  = *(const float4*)&As[cur][k][ty * 8];
            *(float4*)&a[4]  = *(const float4*)&As[cur][k][ty * 8 + 4];
            *(float4*)&bb[0] = *(const float4*)&Bs[cur][k][tx * 8];
            *(float4*)&bb[4] = *(const float4*)&Bs[cur][k][tx * 8 + 4];
#pragma unroll
            for (int i = 0; i < 8; i++)
#pragma unroll
                for (int j = 0; j < 8; j++)
                    acc[i][j] += a[i] * bb[j];
        }
        if (pre) {
            As[nxt][lk + 0][lr] = av.x; As[nxt][lk + 1][lr] = av.y;
            As[nxt][lk + 2][lr] = av.z; As[nxt][lk + 3][lr] = av.w;
            Bs[nxt][lk + 0][lr] = bv.x; Bs[nxt][lk + 1][lr] = bv.y;
            Bs[nxt][lk + 2][lr] = bv.z; Bs[nxt][lk + 3][lr] = bv.w;
        }
        __syncthreads();
    }

    // epilogue: add bias, vectorized stores
#pragma unroll
    for (int i = 0; i < 8; i++) {
        int m = m0 + ty * 8 + i;
#pragma unroll
        for (int jj = 0; jj < 2; jj++) {
            int n = n0 + tx * 8 + jj * 4;
            float4 r;
            r.x = acc[i][jj * 4 + 0] + bias[n + 0];
            r.y = acc[i][jj * 4 + 1] + bias[n + 1];
            r.z = acc[i][jj * 4 + 2] + bias[n + 2];
            r.w = acc[i][jj * 4 + 3] + bias[n + 3];
            *(float4*)(C + (size_t)m * Dm + n) = r;
        }
    }
}

// ---------------------------------------------------------------------------
extern "C" void kernel_launch(void* const* d_in, const int* in_sizes, int n_in,
                              void* d_out, int out_size)
{
    const float* Q    = (const float*)d_in[0];
    const float* K    = (const float*)d_in[1];
    const float* V    = (const float*)d_in[2];
    const float* Wout = (const float*)d_in[3];
    const float* bout = (const float*)d_in[4];
    float* Out = (float*)d_out;

    kv_partial_kernel<<<dim3(BH, SPLIT), 256>>>(K, V);
    kv_reduce_kernel<<<dim3(BH * HD * HD / 256), 256>>>();
    w2_kernel<<<dim3(BH, Dm / 64), 256>>>(Wout);
    out_gemm_kernel<<<dim3(Sl / 128, Dm / 128, Bsz), 256>>>(Q, bout, Out);
}

// round 3
// speedup vs baseline: 2.5815x; 2.5815x over previous
#include <cuda_runtime.h>
#include <cstdint>

#define Bsz 4
#define Sl 4096
#define Dm 1024
#define Hh 16
#define HD 64
#define SPLIT 16
#define BH (Bsz * Hh)

// GEMM-D tiling (mma.sync tf32)
#define TM 256
#define TN 128
#define BK 32
#define NCHUNK (Dm / BK)
#define KPAD 36                      // row stride in floats (144B, 16B-aligned)
#define A_FLOATS (TM * KPAD)
#define B_FLOATS (TN * KPAD)
#define STAGE_FLOATS (A_FLOATS + B_FLOATS)
#define SMEM_DYN (2 * STAGE_FLOATS * 4)

// Scratch (allocation-free rule: device globals)
__device__ float g_KV_part[SPLIT * BH * HD * HD];
__device__ float g_KV[BH * HD * HD];
__device__ float g_W2[Bsz * Dm * Dm];

// ---------------------------------------------------------------------------
// helpers
// ---------------------------------------------------------------------------
__device__ __forceinline__ uint32_t smem_u32(const void* p) {
    uint32_t a;
    asm("{ .reg .u64 t; cvta.to.shared.u64 t, %1; cvt.u32.u64 %0, t; }"
        : "=r"(a) : "l"(p));
    return a;
}
__device__ __forceinline__ void cp16(uint32_t dst, const void* src) {
    asm volatile("cp.async.cg.shared.global [%0], [%1], 16;" :: "r"(dst), "l"(src));
}
__device__ __forceinline__ uint32_t f2tf32(float f) {
    uint32_t r;
    asm("cvt.rna.tf32.f32 %0, %1;" : "=r"(r) : "f"(f));
    return r;
}
__device__ __forceinline__ void mma_tf32_16n8k8(float* c, const uint32_t* a,
                                                const uint32_t* b) {
    asm volatile(
        "mma.sync.aligned.m16n8k8.row.col.f32.tf32.tf32.f32 "
        "{%0,%1,%2,%3}, {%4,%5,%6,%7}, {%8,%9}, {%0,%1,%2,%3};"
        : "+f"(c[0]), "+f"(c[1]), "+f"(c[2]), "+f"(c[3])
        : "r"(a[0]), "r"(a[1]), "r"(a[2]), "r"(a[3]), "r"(b[0]), "r"(b[1]));
}

// ---------------------------------------------------------------------------
// Kernel A: partial KV[b,h,d,e] = sum_{s in split} K[b,s,h*64+d]*V[b,s,h*64+e]
// ---------------------------------------------------------------------------
__global__ __launch_bounds__(256) void kv_partial_kernel(
    const float* __restrict__ K, const float* __restrict__ V)
{
    int bh = blockIdx.x;
    int sp = blockIdx.y;
    int b = bh >> 4, h = bh & 15;
    int t = threadIdx.x;

    __shared__ float Ks[32][64];
    __shared__ float Vs[32][64];

    float acc[4][4] = {};
    int d0 = (t & 15) * 4;
    int e0 = (t >> 4) * 4;

    const float* Kbase = K + ((size_t)b * Sl) * Dm + h * HD;
    const float* Vbase = V + ((size_t)b * Sl) * Dm + h * HD;
    int s_begin = sp * (Sl / SPLIT);

    for (int sc = 0; sc < (Sl / SPLIT); sc += 32) {
#pragma unroll
        for (int r = 0; r < 2; r++) {
            int idx = t + r * 256;
            int row = idx >> 4;
            int c4 = (idx & 15) * 4;
            size_t goff = (size_t)(s_begin + sc + row) * Dm + c4;
            float4 kv4 = *(const float4*)(Kbase + goff);
            float4 vv4 = *(const float4*)(Vbase + goff);
            *(float4*)&Ks[row][c4] = kv4;
            *(float4*)&Vs[row][c4] = vv4;
        }
        __syncthreads();
#pragma unroll
        for (int ss = 0; ss < 32; ss++) {
            float4 kd = *(const float4*)&Ks[ss][d0];
            float4 ve = *(const float4*)&Vs[ss][e0];
            float kk[4] = {kd.x, kd.y, kd.z, kd.w};
            float vv[4] = {ve.x, ve.y, ve.z, ve.w};
#pragma unroll
            for (int i = 0; i < 4; i++)
#pragma unroll
                for (int j = 0; j < 4; j++)
                    acc[i][j] += kk[i] * vv[j];
        }
        __syncthreads();
    }

    float* out = g_KV_part + ((size_t)sp * BH + bh) * (HD * HD);
#pragma unroll
    for (int i = 0; i < 4; i++)
#pragma unroll
        for (int j = 0; j < 4; j++)
            out[(d0 + i) * HD + (e0 + j)] = acc[i][j];
}

// ---------------------------------------------------------------------------
// Kernel B: deterministic reduction of SPLIT partials
// ---------------------------------------------------------------------------
__global__ __launch_bounds__(256) void kv_reduce_kernel()
{
    int idx = blockIdx.x * 256 + threadIdx.x;
    float s = 0.f;
#pragma unroll
    for (int p = 0; p < SPLIT; p++)
        s += g_KV_part[(size_t)p * (BH * HD * HD) + idx];
    g_KV[idx] = s;
}

// ---------------------------------------------------------------------------
// Kernel C: W2[b][o][h*64+d] = sum_e KV[b,h,d,e] * W[o*Dm + h*64 + e]
// ---------------------------------------------------------------------------
__global__ __launch_bounds__(256) void w2_kernel(const float* __restrict__ W)
{
    int bh = blockIdx.x;
    int ot = blockIdx.y;
    int b = bh >> 4, h = bh & 15;
    int t = threadIdx.x;
    int o_base = ot * 64;

    __shared__ float KVt[64][68];
    __shared__ float WsT[64][68];

    for (int idx = t; idx < 4096; idx += 256) {
        int r = idx >> 6;
        int c = idx & 63;
        KVt[c][r] = g_KV[(size_t)bh * 4096 + idx];
        WsT[c][r] = W[(size_t)(o_base + r) * Dm + h * HD + c];
    }
    __syncthreads();

    int d0 = (t & 15) * 4;
    int o0 = (t >> 4) * 4;
    float acc[4][4] = {};
#pragma unroll 8
    for (int e = 0; e < 64; e++) {
        float4 wv = *(const float4*)&WsT[e][o0];
        float4 kv = *(const float4*)&KVt[e][d0];
        float ww[4] = {wv.x, wv.y, wv.z, wv.w};
        float kk[4] = {kv.x, kv.y, kv.z, kv.w};
#pragma unroll
        for (int i = 0; i < 4; i++)
#pragma unroll
            for (int j = 0; j < 4; j++)
                acc[i][j] += ww[i] * kk[j];
    }
#pragma unroll
    for (int i = 0; i < 4; i++)
#pragma unroll
        for (int j = 0; j < 4; j++)
            g_W2[((size_t)b * Dm + (o_base + o0 + i)) * Dm + h * HD + d0 + j] = acc[i][j];
}

// ---------------------------------------------------------------------------
// Kernel D: out[b,m,n] = sum_k Q[b,m,k]*W2[b,n,k] + bias[n]
// mma.sync tf32 m16n8k8. CTA tile 256x128, BK=32, 512 thr (16 warps, 4x4),
// warp tile 64x32, 2-stage cp.async double buffer.
// grid (Sl/TM, Dm/TN, Bsz).
// ---------------------------------------------------------------------------
__global__ __launch_bounds__(512, 1) void out_gemm_tc(
    const float* __restrict__ Q, const float* __restrict__ bias,
    float* __restrict__ Out)
{
    extern __shared__ float smem[];

    const int t   = threadIdx.x;
    const int wid = t >> 5;
    const int lid = t & 31;
    const int g   = lid >> 2;       // 0..7
    const int tig = lid & 3;        // 0..3
    const int wm  = wid >> 2;       // 0..3 (M)
    const int wn  = wid & 3;        // 0..3 (N)

    const int m0 = blockIdx.x * TM;
    const int n0 = blockIdx.y * TN;
    const int b  = blockIdx.z;

    const float* Ag = Q    + (size_t)b * Sl * Dm + (size_t)m0 * Dm;
    const float* Bg = g_W2 + (size_t)b * Dm * Dm + (size_t)n0 * Dm;

    float* sA[2] = { smem,                smem + STAGE_FLOATS };
    float* sB[2] = { smem + A_FLOATS,     smem + STAGE_FLOATS + A_FLOATS };
    uint32_t uA[2] = { smem_u32(sA[0]), smem_u32(sA[1]) };
    uint32_t uB[2] = { smem_u32(sB[0]), smem_u32(sB[1]) };

    // stage load: A = 256 rows x 32 floats, B = 128 rows x 32 floats
    auto load_stage = [&](int s, int k0) {
#pragma unroll
        for (int i = 0; i < 4; i++) {              // A: 2048 16B-chunks / 512 thr
            int idx = t + (i << 9);
            int row = idx >> 3, c = idx & 7;
            cp16(uA[s] + row * (KPAD * 4) + c * 16,
                 Ag + (size_t)row * Dm + k0 + c * 4);
        }
#pragma unroll
        for (int i = 0; i < 2; i++) {              // B: 1024 chunks
            int idx = t + (i << 9);
            int row = idx >> 3, c = idx & 7;
            cp16(uB[s] + row * (KPAD * 4) + c * 16,
                 Bg + (size_t)row * Dm + k0 + c * 4);
        }
    };

    float acc[4][4][4] = {};

    load_stage(0, 0);
    asm volatile("cp.async.commit_group;" ::: "memory");
    load_stage(1, BK);
    asm volatile("cp.async.commit_group;" ::: "memory");

    for (int i = 0; i < NCHUNK; i++) {
        const int s = i & 1;
        asm volatile("cp.async.wait_group 1;" ::: "memory");
        __syncthreads();

        const float* As = sA[s];
        const float* Bs = sB[s];
#pragma unroll
        for (int ks = 0; ks < 4; ks++) {
            const int k0 = ks * 8;
            uint32_t af[4][4];
#pragma unroll
            for (int mi = 0; mi < 4; mi++) {
                int row = wm * 64 + mi * 16;
                af[mi][0] = f2tf32(As[(row + g)     * KPAD + k0 + tig]);
                af[mi][1] = f2tf32(As[(row + g + 8) * KPAD + k0 + tig]);
                af[mi][2] = f2tf32(As[(row + g)     * KPAD + k0 + tig + 4]);
                af[mi][3] = f2tf32(As[(row + g + 8) * KPAD + k0 + tig + 4]);
            }
            uint32_t bf[4][2];
#pragma unroll
            for (int ni = 0; ni < 4; ni++) {
                int rn = wn * 32 + ni * 8;
                bf[ni][0] = f2tf32(Bs[(rn + g) * KPAD + k0 + tig]);
                bf[ni][1] = f2tf32(Bs[(rn + g) * KPAD + k0 + tig + 4]);
            }
#pragma unroll
            for (int mi = 0; mi < 4; mi++)
#pragma unroll
                for (int ni = 0; ni < 4; ni++)
                    mma_tf32_16n8k8(acc[mi][ni], af[mi], bf[ni]);
        }

        __syncthreads();
        if (i + 2 < NCHUNK)
            load_stage(s, (i + 2) * BK);
        asm volatile("cp.async.commit_group;" ::: "memory");
    }

    // epilogue: add bias, store (float2 per fragment half)
    float* C = Out + (size_t)b * Sl * Dm;
#pragma unroll
    for (int mi = 0; mi < 4; mi++) {
        int row = m0 + wm * 64 + mi * 16 + g;
#pragma unroll
        for (int ni = 0; ni < 4; ni++) {
            int col = n0 + wn * 32 + ni * 8 + tig * 2;
            float bx = bias[col], by = bias[col + 1];
            float2 r0 = { acc[mi][ni][0] + bx, acc[mi][ni][1] + by };
            float2 r1 = { acc[mi][ni][2] + bx, acc[mi][ni][3] + by };
            *(float2*)(C + (size_t)row * Dm + col)       = r0;
            *(float2*)(C + (size_t)(row + 8) * Dm + col) = r1;
        }
    }
}

// ---------------------------------------------------------------------------
extern "C" void kernel_launch(void* const* d_in, const int* in_sizes, int n_in,
                              void* d_out, int out_size)
{
    const float* Q    = (const float*)d_in[0];
    const float* K    = (const float*)d_in[1];
    const float* V    = (const float*)d_in[2];
    const float* Wout = (const float*)d_in[3];
    const float* bout = (const float*)d_in[4];
    float* Out = (float*)d_out;

    static bool attr_done = false;
    if (!attr_done) {
        cudaFuncSetAttribute(out_gemm_tc,
                             cudaFuncAttributeMaxDynamicSharedMemorySize, SMEM_DYN);
        attr_done = true;
    }

    kv_partial_kernel<<<dim3(BH, SPLIT), 256>>>(K, V);
    kv_reduce_kernel<<<dim3(BH * HD * HD / 256), 256>>>();
    w2_kernel<<<dim3(BH, Dm / 64), 256>>>(Wout);
    out_gemm_tc<<<dim3(Sl / TM, Dm / TN, Bsz), 512, SMEM_DYN>>>(Q, bout, Out);
}